// round 5
// baseline (speedup 1.0000x reference)
#include <cuda_runtime.h>

// Problem constants (DynamicNeuralGraph_57758720197073)
#define NN   256    // num neurons
#define IDIM 784    // input dim
#define HDIM 128    // hidden dim
#define BDIM 256    // batch
#define PCH  8      // number of edge chunks
#define LMAX 512    // max edges per chunk (E=4096 / 8)

// Scratch (no allocations allowed -> __device__ globals)
__device__ float g_A[PCH][NN * NN];      // chunk transfer matrices, column-major: [p][j*NN + i]
__device__ float g_c[NN];                // neuron coefficient vector
__device__ float g_beff[HDIM];           // effective bias
__device__ float g_weff[IDIM * HDIM];    // effective weight matrix

// ---------------------------------------------------------------------------
// K1: build chunk transfer matrices.
// Reverse recurrence c[s] += w*c[t] over chunk == left-multiply identity by
// (I + w e_s e_t^T) per edge: row_s += w * row_t, applied in reverse edge order.
// 64 CTAs = 8 chunks x 8 column-groups of 32 columns. Serial chain per chunk is
// L x (LDS 29 + FFMA 4 + STS); edge data is prefetched one iteration ahead into
// registers so it stays off the critical path (es/et/ewv are distinct static
// __shared__ arrays -> no alias hazard with rows[]).
// ---------------------------------------------------------------------------
__global__ void k_chunks(const int* __restrict__ eidx,
                         const float* __restrict__ ew, int E) {
    __shared__ float rows[NN * 33];      // 32 columns + stride-33 (conflict-free transpose)
    __shared__ int   es[LMAX + 1];
    __shared__ int   et[LMAX + 1];
    __shared__ float ewv[LMAX + 1];

    const int p  = blockIdx.x >> 3;      // chunk id
    const int cg = blockIdx.x & 7;       // column group
    const int j  = threadIdx.x;          // 0..31 (one column per lane)
    const int jg = cg * 32 + j;          // global column

    // identity init for this CTA's 32 columns
    #pragma unroll 8
    for (int i = 0; i < NN; i++)
        rows[i * 33 + j] = (i == jg) ? 1.0f : 0.0f;

    int L  = (E + PCH - 1) / PCH;
    if (L > LMAX) L = LMAX;              // safety (E is 4096 for this problem)
    const int r0 = p * L;
    int cnt = E - r0;
    if (cnt > L) cnt = L;
    if (cnt < 0) cnt = 0;

    // stage this chunk's edges in REVERSE global order
    for (int r = j; r < cnt; r += 32) {
        int k   = E - 1 - (r0 + r);
        es[r]   = eidx[k];               // src
        et[r]   = eidx[E + k];           // tgt
        ewv[r]  = ew[k];
    }
    __syncthreads();

    // serial chain, software-pipelined edge fetch
    int   s = es[0], t = et[0];
    float w = ewv[0];
    for (int r = 0; r < cnt; r++) {
        int   sn = es[r + 1];
        int   tn = et[r + 1];
        float wn = ewv[r + 1];
        float tv = rows[t * 33 + j];
        rows[s * 33 + j] += w * tv;      // c[s] += w * c[t]
        s = sn; t = tn; w = wn;
    }
    __syncthreads();

    // write out column-major g_A[p][jc*NN + i], coalesced over i
    float* out = g_A[p];
    #pragma unroll 4
    for (int jl = 0; jl < 32; jl++) {
        const int jc = cg * 32 + jl;
        #pragma unroll
        for (int ib = 0; ib < NN; ib += 32)
            out[jc * NN + ib + j] = rows[(ib + j) * 33 + jl];
    }
}

// ---------------------------------------------------------------------------
// K2: combine. v = u; for p: v <- A_p v. Then c = v, beff = sum_m c[m]*b[m].
// One CTA, 1024 threads: 64 row-groups (4 rows each, float4) x 16 j-segments.
// g_A is L2-resident (just written by K1).
// ---------------------------------------------------------------------------
__global__ void k_combine(const float* __restrict__ bb) {
    __shared__ float v[NN];
    __shared__ float ps[16][NN];

    const int tid = threadIdx.x;
    if (tid < NN) v[tid] = 1.0f / (float)NN;   // u = mean functional
    __syncthreads();

    const int i4  = tid & 63;    // row group (rows i4*4 .. i4*4+3)
    const int seg = tid >> 6;    // j segment (cols seg*16 .. +15)

    for (int p = 0; p < PCH; p++) {
        const float* A = g_A[p];
        float ax = 0.f, ay = 0.f, az = 0.f, aw = 0.f;
        #pragma unroll
        for (int jj = 0; jj < 16; jj++) {
            const int jc = seg * 16 + jj;
            const float vj = v[jc];
            const float4 a = *(const float4*)(A + jc * NN + i4 * 4);
            ax = fmaf(a.x, vj, ax);
            ay = fmaf(a.y, vj, ay);
            az = fmaf(a.z, vj, az);
            aw = fmaf(a.w, vj, aw);
        }
        *(float4*)&ps[seg][i4 * 4] = make_float4(ax, ay, az, aw);
        __syncthreads();
        if (tid < NN) {
            float sum = 0.f;
            #pragma unroll
            for (int sg = 0; sg < 16; sg++) sum += ps[sg][tid];
            v[tid] = sum;
        }
        __syncthreads();
    }

    if (tid < NN) g_c[tid] = v[tid];

    // beff[h] = sum_m v[m] * b[m][h]
    const int h  = tid & 127;
    const int ms = tid >> 7;                 // 0..7, each covers 32 m's
    float acc = 0.f;
    #pragma unroll 8
    for (int mm = 0; mm < 32; mm++) {
        const int m = ms * 32 + mm;
        acc = fmaf(v[m], bb[m * HDIM + h], acc);
    }
    ps[ms][h] = acc;
    __syncthreads();
    if (tid < HDIM) {
        float sum = 0.f;
        #pragma unroll
        for (int sg = 0; sg < 8; sg++) sum += ps[sg][tid];
        g_beff[tid] = sum;
    }
}

// ---------------------------------------------------------------------------
// K3: Weff[i][h] = sum_m c[m] * W[m][i][h].  HBM-bound: streams 103 MB once.
// 196 CTAs x 128 threads; warp <-> input row i, lane <-> 4 h's (float4,
// 512B coalesced per warp per m).
// ---------------------------------------------------------------------------
__global__ void k_weff(const float* __restrict__ W) {
    __shared__ float c[NN];
    const int tid = threadIdx.x;             // 0..127
    c[tid]       = g_c[tid];
    c[tid + 128] = g_c[tid + 128];
    __syncthreads();

    const int warp = tid >> 5;
    const int lane = tid & 31;
    const int i    = blockIdx.x * 4 + warp;  // 0..783
    const float* base = W + (size_t)i * HDIM + lane * 4;

    float ax = 0.f, ay = 0.f, az = 0.f, aw = 0.f;
    #pragma unroll 8
    for (int m = 0; m < NN; m++) {
        const float cm = c[m];
        const float4 wv = *(const float4*)(base + (size_t)m * (IDIM * HDIM));
        ax = fmaf(cm, wv.x, ax);
        ay = fmaf(cm, wv.y, ay);
        az = fmaf(cm, wv.z, az);
        aw = fmaf(cm, wv.w, aw);
    }
    *(float4*)(g_weff + i * HDIM + lane * 4) = make_float4(ax, ay, az, aw);
}

// ---------------------------------------------------------------------------
// K4: out[b][h] = beff[h] + sum_i x[b][i] * Weff[i][h].
// 32 CTAs x 256 threads: CTA covers 8 batch rows x all 128 h (thread = 4 h).
// Weff (401 KB) is L2-resident from K3.
// ---------------------------------------------------------------------------
__global__ void k_gemm(const float* __restrict__ x, float* __restrict__ out) {
    __shared__ float xs[8][IDIM];
    const int tid = threadIdx.x;             // 0..255
    const int b0  = blockIdx.x * 8;

    #pragma unroll
    for (int bl = 0; bl < 8; bl++)
        for (int i = tid; i < IDIM; i += 256)
            xs[bl][i] = x[(b0 + bl) * IDIM + i];
    __syncthreads();

    const int bl = tid >> 5;                 // batch row within tile
    const int h4 = tid & 31;                 // h quad
    const float* wp = g_weff + h4 * 4;

    float ax = 0.f, ay = 0.f, az = 0.f, aw = 0.f;
    #pragma unroll 8
    for (int i = 0; i < IDIM; i++) {
        const float xv = xs[bl][i];
        const float4 wv = *(const float4*)(wp + i * HDIM);
        ax = fmaf(xv, wv.x, ax);
        ay = fmaf(xv, wv.y, ay);
        az = fmaf(xv, wv.z, az);
        aw = fmaf(xv, wv.w, aw);
    }
    const float4 be = *(const float4*)(g_beff + h4 * 4);
    *(float4*)(out + (b0 + bl) * HDIM + h4 * 4) =
        make_float4(ax + be.x, ay + be.y, az + be.z, aw + be.w);
}

// ---------------------------------------------------------------------------
// Inputs (metadata order): x (B,I) f32 | W (N,I,H) f32 | b (N,H) f32 |
// edge_index (2,E) i32 | edge_weights (E,) f32.  Output: (B,H) f32.
// ---------------------------------------------------------------------------
extern "C" void kernel_launch(void* const* d_in, const int* in_sizes, int n_in,
                              void* d_out, int out_size) {
    const float* x    = (const float*)d_in[0];
    const float* W    = (const float*)d_in[1];
    const float* b    = (const float*)d_in[2];
    const int*   eidx = (const int*)d_in[3];
    const float* ew   = (const float*)d_in[4];
    const int    E    = in_sizes[4];         // 4096

    k_chunks <<<64, 32>>>(eidx, ew, E);      // parallel chunk transfer matrices
    k_combine<<<1, 1024>>>(b);               // c vector + beff
    k_weff   <<<196, 128>>>(W);              // Weff = sum c[m] W[m]  (HBM-bound)
    k_gemm   <<<32, 256>>>(x, (float*)d_out);
}

// round 6
// speedup vs baseline: 1.5759x; 1.5759x over previous
#include <cuda_runtime.h>

// Problem constants (DynamicNeuralGraph_57758720197073)
#define NN   256    // num neurons
#define IDIM 784    // input dim
#define HDIM 128    // hidden dim
#define BDIM 256    // batch
#define PCH  8      // number of edge chunks
#define LMAX 512    // max edges per chunk (E=4096 / 8)

// Scratch (no allocations allowed -> __device__ globals)
__device__ float g_A[PCH][NN * NN];      // chunk transfer matrices, column-major: [p][j*NN + i]
__device__ float g_c[NN];                // neuron coefficient vector
__device__ float g_beff[HDIM];           // effective bias
__device__ float g_weff[IDIM * HDIM];    // effective weight matrix

// ---------------------------------------------------------------------------
// K1: build chunk transfer matrices.
// Reverse recurrence c[s] += w*c[t] over chunk == left-multiply identity by
// (I + w e_s e_t^T) per edge: row_s += w * row_t, in reverse edge order.
// 64 CTAs = 8 chunks x 8 column-groups of 32 columns.
// ---------------------------------------------------------------------------
__global__ void k_chunks(const int* __restrict__ eidx,
                         const float* __restrict__ ew, int E) {
    __shared__ float rows[NN * 33];      // 32 columns + stride-33 (conflict-free transpose)
    __shared__ int   es[LMAX + 1];
    __shared__ int   et[LMAX + 1];
    __shared__ float ewv[LMAX + 1];

    const int p  = blockIdx.x >> 3;      // chunk id
    const int cg = blockIdx.x & 7;       // column group
    const int j  = threadIdx.x;          // 0..31 (one column per lane)
    const int jg = cg * 32 + j;          // global column

    // identity init for this CTA's 32 columns
    #pragma unroll 8
    for (int i = 0; i < NN; i++)
        rows[i * 33 + j] = (i == jg) ? 1.0f : 0.0f;

    int L  = (E + PCH - 1) / PCH;
    if (L > LMAX) L = LMAX;              // safety (E is 4096 for this problem)
    const int r0 = p * L;
    int cnt = E - r0;
    if (cnt > L) cnt = L;
    if (cnt < 0) cnt = 0;

    // stage this chunk's edges in REVERSE global order
    for (int r = j; r < cnt; r += 32) {
        int k   = E - 1 - (r0 + r);
        es[r]   = eidx[k];               // src
        et[r]   = eidx[E + k];           // tgt
        ewv[r]  = ew[k];
    }
    __syncthreads();

    // serial chain, software-pipelined edge fetch
    int   s = es[0], t = et[0];
    float w = ewv[0];
    for (int r = 0; r < cnt; r++) {
        int   sn = es[r + 1];
        int   tn = et[r + 1];
        float wn = ewv[r + 1];
        float tv = rows[t * 33 + j];
        rows[s * 33 + j] += w * tv;      // c[s] += w * c[t]
        s = sn; t = tn; w = wn;
    }
    __syncthreads();

    // write out column-major g_A[p][jc*NN + i], coalesced over i
    float* out = g_A[p];
    #pragma unroll 4
    for (int jl = 0; jl < 32; jl++) {
        const int jc = cg * 32 + jl;
        #pragma unroll
        for (int ib = 0; ib < NN; ib += 32)
            out[jc * NN + ib + j] = rows[(ib + j) * 33 + jl];
    }
}

// ---------------------------------------------------------------------------
// K2: combine. v = u; for p: v <- A_p v. Then c = v, beff = sum_m c[m]*b[m].
// One CTA, 1024 threads. g_A is L2-resident (just written by K1).
// ---------------------------------------------------------------------------
__global__ void k_combine(const float* __restrict__ bb) {
    __shared__ float v[NN];
    __shared__ float ps[16][NN];

    const int tid = threadIdx.x;
    if (tid < NN) v[tid] = 1.0f / (float)NN;   // u = mean functional
    __syncthreads();

    const int i4  = tid & 63;    // row group (rows i4*4 .. i4*4+3)
    const int seg = tid >> 6;    // j segment (cols seg*16 .. +15)

    for (int p = 0; p < PCH; p++) {
        const float* A = g_A[p];
        float ax = 0.f, ay = 0.f, az = 0.f, aw = 0.f;
        #pragma unroll
        for (int jj = 0; jj < 16; jj++) {
            const int jc = seg * 16 + jj;
            const float vj = v[jc];
            const float4 a = *(const float4*)(A + jc * NN + i4 * 4);
            ax = fmaf(a.x, vj, ax);
            ay = fmaf(a.y, vj, ay);
            az = fmaf(a.z, vj, az);
            aw = fmaf(a.w, vj, aw);
        }
        *(float4*)&ps[seg][i4 * 4] = make_float4(ax, ay, az, aw);
        __syncthreads();
        if (tid < NN) {
            float sum = 0.f;
            #pragma unroll
            for (int sg = 0; sg < 16; sg++) sum += ps[sg][tid];
            v[tid] = sum;
        }
        __syncthreads();
    }

    if (tid < NN) g_c[tid] = v[tid];

    // beff[h] = sum_m v[m] * b[m][h]
    const int h  = tid & 127;
    const int ms = tid >> 7;                 // 0..7, each covers 32 m's
    float acc = 0.f;
    #pragma unroll 8
    for (int mm = 0; mm < 32; mm++) {
        const int m = ms * 32 + mm;
        acc = fmaf(v[m], bb[m * HDIM + h], acc);
    }
    ps[ms][h] = acc;
    __syncthreads();
    if (tid < HDIM) {
        float sum = 0.f;
        #pragma unroll
        for (int sg = 0; sg < 8; sg++) sum += ps[sg][tid];
        g_beff[tid] = sum;
    }
}

// ---------------------------------------------------------------------------
// K3: Weff[i][h] = sum_m c[m] * W[m][i][h].  HBM-bound: streams 103 MB once.
// 196 CTAs x 128 threads; warp <-> input row i, lane <-> 4 h's (float4).
// ---------------------------------------------------------------------------
__global__ void k_weff(const float* __restrict__ W) {
    __shared__ float c[NN];
    const int tid = threadIdx.x;             // 0..127
    c[tid]       = g_c[tid];
    c[tid + 128] = g_c[tid + 128];
    __syncthreads();

    const int warp = tid >> 5;
    const int lane = tid & 31;
    const int i    = blockIdx.x * 4 + warp;  // 0..783
    const float* base = W + (size_t)i * HDIM + lane * 4;

    float ax = 0.f, ay = 0.f, az = 0.f, aw = 0.f;
    #pragma unroll 8
    for (int m = 0; m < NN; m++) {
        const float cm = c[m];
        const float4 wv = *(const float4*)(base + (size_t)m * (IDIM * HDIM));
        ax = fmaf(cm, wv.x, ax);
        ay = fmaf(cm, wv.y, ay);
        az = fmaf(cm, wv.z, az);
        aw = fmaf(cm, wv.w, aw);
    }
    *(float4*)(g_weff + i * HDIM + lane * 4) = make_float4(ax, ay, az, aw);
}

// ---------------------------------------------------------------------------
// K4 v2: out[b][h] = beff[h] + sum_i x[b][i] * Weff[i][h].
// Restructured for MLP + occupancy (v1 was latency-serialized at 125us):
//   grid 64 CTAs (4 batch rows each), 256 threads = 8 warps.
//   warp = i-parity (i = warp, warp+8, ... -> 98 i's), lane = h-quad.
//   Each thread register-blocks 4 batch rows x 4 h = 16 accumulators, so one
//   coalesced 512B Weff load per warp-iter feeds 16 FFMAs. unroll 7 keeps
//   >=7 independent LDG.128 in flight -> latency chain ~98/7*240 cyc.
//   Cross-warp reduction over i-parity in shared memory. No atomics.
// ---------------------------------------------------------------------------
__global__ void __launch_bounds__(256) k_gemm(const float* __restrict__ x,
                                              float* __restrict__ out) {
    __shared__ float xs[4][IDIM];            // 12.5 KB
    __shared__ float ps[8][4 * HDIM];        // 16 KB: per-warp partials

    const int tid = threadIdx.x;             // 0..255
    const int b0  = blockIdx.x * 4;

    // stage 4 batch rows of x (coalesced)
    for (int v = tid; v < 4 * IDIM; v += 256) {
        const int bl = v / IDIM;
        const int i  = v - bl * IDIM;
        xs[bl][i] = x[(b0 + bl) * IDIM + i];
    }
    __syncthreads();

    const int warp = tid >> 5;               // i-parity 0..7
    const int lane = tid & 31;               // h-quad
    const float* wp = g_weff + lane * 4;

    float a0x=0.f,a0y=0.f,a0z=0.f,a0w=0.f;
    float a1x=0.f,a1y=0.f,a1z=0.f,a1w=0.f;
    float a2x=0.f,a2y=0.f,a2z=0.f,a2w=0.f;
    float a3x=0.f,a3y=0.f,a3z=0.f,a3w=0.f;

    // 98 iterations: i = warp + k*8  (IDIM = 784 = 98*8)
    #pragma unroll 7
    for (int k = 0; k < IDIM / 8; k++) {
        const int i = warp + k * 8;
        const float4 wv = *(const float4*)(wp + i * HDIM);
        const float x0 = xs[0][i];
        const float x1 = xs[1][i];
        const float x2 = xs[2][i];
        const float x3 = xs[3][i];
        a0x = fmaf(x0, wv.x, a0x); a0y = fmaf(x0, wv.y, a0y);
        a0z = fmaf(x0, wv.z, a0z); a0w = fmaf(x0, wv.w, a0w);
        a1x = fmaf(x1, wv.x, a1x); a1y = fmaf(x1, wv.y, a1y);
        a1z = fmaf(x1, wv.z, a1z); a1w = fmaf(x1, wv.w, a1w);
        a2x = fmaf(x2, wv.x, a2x); a2y = fmaf(x2, wv.y, a2y);
        a2z = fmaf(x2, wv.z, a2z); a2w = fmaf(x2, wv.w, a2w);
        a3x = fmaf(x3, wv.x, a3x); a3y = fmaf(x3, wv.y, a3y);
        a3z = fmaf(x3, wv.z, a3z); a3w = fmaf(x3, wv.w, a3w);
    }

    // per-warp partials -> smem
    *(float4*)&ps[warp][0 * HDIM + lane * 4] = make_float4(a0x, a0y, a0z, a0w);
    *(float4*)&ps[warp][1 * HDIM + lane * 4] = make_float4(a1x, a1y, a1z, a1w);
    *(float4*)&ps[warp][2 * HDIM + lane * 4] = make_float4(a2x, a2y, a2z, a2w);
    *(float4*)&ps[warp][3 * HDIM + lane * 4] = make_float4(a3x, a3y, a3z, a3w);
    __syncthreads();

    // reduce over 8 warps: 512 outputs, 2 per thread
    #pragma unroll
    for (int o = tid; o < 4 * HDIM; o += 256) {
        float s = 0.f;
        #pragma unroll
        for (int wv = 0; wv < 8; wv++) s += ps[wv][o];
        const int bl = o >> 7;               // 0..3
        const int h  = o & 127;
        out[(b0 + bl) * HDIM + h] = s + g_beff[h];
    }
}

// ---------------------------------------------------------------------------
// Inputs (metadata order): x (B,I) f32 | W (N,I,H) f32 | b (N,H) f32 |
// edge_index (2,E) i32 | edge_weights (E,) f32.  Output: (B,H) f32.
// ---------------------------------------------------------------------------
extern "C" void kernel_launch(void* const* d_in, const int* in_sizes, int n_in,
                              void* d_out, int out_size) {
    const float* x    = (const float*)d_in[0];
    const float* W    = (const float*)d_in[1];
    const float* b    = (const float*)d_in[2];
    const int*   eidx = (const int*)d_in[3];
    const float* ew   = (const float*)d_in[4];
    const int    E    = in_sizes[4];         // 4096

    k_chunks <<<64, 32>>>(eidx, ew, E);      // parallel chunk transfer matrices
    k_combine<<<1, 1024>>>(b);               // c vector + beff
    k_weff   <<<196, 128>>>(W);              // Weff = sum c[m] W[m]  (HBM-bound)
    k_gemm   <<<64, 256>>>(x, (float*)d_out);
}